// round 1
// baseline (speedup 1.0000x reference)
#include <cuda_runtime.h>

// out[b,f] = x[b,f] * exp( (log_sigma[f] < 1.0f) ? 1 : 0 )
//          = x[b,f] * (log_sigma[f] < 1.0f ? e : 1.0f)
//
// BATCH = 65536, N_FEATURES = 4096  -> 2^28 fp32 elements = 2^26 float4.
// Pure HBM-streaming kernel: 1 GiB in + 1 GiB out.

#define N_FEATURES 4096
#define VEC4_PER_ROW (N_FEATURES / 4)          // 1024, power of two
#define TOTAL_VEC4 (65536LL * VEC4_PER_ROW)    // 2^26

__global__ void __launch_bounds__(256)
svdropout2d_kernel(const float4* __restrict__ x,
                   const float4* __restrict__ log_sigma,
                   float4* __restrict__ out)
{
    const float E = 2.71828182845904523536f;

    long long i = (long long)blockIdx.x * blockDim.x + threadIdx.x;
    if (i >= TOTAL_VEC4) return;

    // column (in float4 units) within the row — power-of-two mask, no div
    int c = (int)(i & (VEC4_PER_ROW - 1));

    float4 ls = log_sigma[c];       // 16 KB total, L1-resident after warmup
    float4 v  = x[i];

    v.x *= (ls.x < 1.0f) ? E : 1.0f;
    v.y *= (ls.y < 1.0f) ? E : 1.0f;
    v.z *= (ls.z < 1.0f) ? E : 1.0f;
    v.w *= (ls.w < 1.0f) ? E : 1.0f;

    out[i] = v;
}

extern "C" void kernel_launch(void* const* d_in, const int* in_sizes, int n_in,
                              void* d_out, int out_size)
{
    const float4* x  = (const float4*)d_in[0];
    const float4* ls = (const float4*)d_in[1];
    float4* out      = (float4*)d_out;

    const long long total = TOTAL_VEC4;
    const int threads = 256;
    const long long blocks = (total + threads - 1) / threads;  // 262144

    svdropout2d_kernel<<<(unsigned)blocks, threads>>>(x, ls, out);
}